// round 4
// baseline (speedup 1.0000x reference)
#include <cuda_runtime.h>
#include <cuda_bf16.h>

#define DIM   2048
#define BATCH 32
#define KTOP  256
#define LOG2E 1.44269504f

// Two j-half partial sums of Bsum (pre-scaled by log2e): [jh][b][i]
__device__ float g_part[2 * BATCH * DIM];

__device__ __forceinline__ unsigned long long f32x2_add(unsigned long long a,
                                                        unsigned long long b) {
    unsigned long long r;
    asm("add.rn.f32x2 %0, %1, %2;" : "=l"(r) : "l"(a), "l"(b));
    return r;
}
__device__ __forceinline__ float ex2f(float x) {
    float r;
    asm("ex2.approx.ftz.f32 %0, %1;" : "=f"(r) : "f"(x));
    return r;
}
__device__ __forceinline__ float rcpf(float x) {
    float r;
    asm("rcp.approx.f32 %0, %1;" : "=f"(r) : "f"(x));
    return r;
}

// ---------------------------------------------------------------------------
// Kernel 1: all-pairs |diff| partial row sums, packed f32x2.
// Grid (32 i-chunks, 2 j-halves, 32 b), 1 warp per block (2048 blocks ->
// ~14 warps/SM -> fma pipe fully fed). Each thread owns 2 packed i's and
// sweeps 1024 j's staged in smem as negated duplicated pairs (-sj,-sj) so the
// inner loop is pure add2 / LOP3 / broadcast-LDS. Two-level accumulation
// (fold every 32 j) keeps fp32 error well under reference tolerance.
// ---------------------------------------------------------------------------
__global__ __launch_bounds__(32) void bsum_kernel(const float* __restrict__ scores) {
    __shared__ float nd[DIM];            // 1024 j * 2 copies = 8KB
    const int ic = blockIdx.x;           // i chunk (64 i's)
    const int jh = blockIdx.y;           // j half
    const int b  = blockIdx.z;
    const int lane = threadIdx.x;

    const float* row = scores + (b << 11);

    // stage negated duplicated j-half: nd[2j]=nd[2j+1] = -s[jh*1024+j]
    {
        const float4* r4 = (const float4*)(row + (jh << 10));
        float4* n4 = (float4*)nd;
        #pragma unroll
        for (int c = 0; c < 8; c++) {
            float4 v = r4[c * 32 + lane];
            n4[(c * 32 + lane) * 2 + 0] = make_float4(-v.x, -v.x, -v.y, -v.y);
            n4[(c * 32 + lane) * 2 + 1] = make_float4(-v.z, -v.z, -v.w, -v.w);
        }
    }
    __syncwarp();

    const int i0 = (ic << 6) + lane * 2;
    unsigned long long X;
    {
        float2 xv = ((const float2*)row)[(ic << 5) + lane];
        X = ((unsigned long long)__float_as_uint(xv.y) << 32) | __float_as_uint(xv.x);
    }
    const unsigned long long ABSM = 0x7FFFFFFF7FFFFFFFULL;

    const ulonglong2* nd2 = (const ulonglong2*)nd;   // 2 duplicated j's per entry

    unsigned long long m0 = 0ULL, m1 = 0ULL, m2 = 0ULL, m3 = 0ULL;
    for (int o = 0; o < 32; o++) {                   // 32 outer folds
        unsigned long long a0 = 0ULL, a1 = 0ULL, a2 = 0ULL, a3 = 0ULL;
        #pragma unroll
        for (int t = 0; t < 8; t++) {                // 8 iters x 4 j = 32 j
            ulonglong2 A = nd2[(o * 8 + t) * 2 + 0]; // broadcast LDS.128
            ulonglong2 B = nd2[(o * 8 + t) * 2 + 1];
            a0 = f32x2_add(a0, f32x2_add(X, A.x) & ABSM);
            a1 = f32x2_add(a1, f32x2_add(X, A.y) & ABSM);
            a2 = f32x2_add(a2, f32x2_add(X, B.x) & ABSM);
            a3 = f32x2_add(a3, f32x2_add(X, B.y) & ABSM);
        }
        m0 = f32x2_add(m0, a0);
        m1 = f32x2_add(m1, a1);
        m2 = f32x2_add(m2, a2);
        m3 = f32x2_add(m3, a3);
    }

    unsigned long long m = f32x2_add(f32x2_add(m0, m1), f32x2_add(m2, m3));
    float r0 = __uint_as_float((unsigned int)m) * LOG2E;
    float r1 = __uint_as_float((unsigned int)(m >> 32)) * LOG2E;

    float2* dst = (float2*)(g_part + ((jh * BATCH + b) << 11));
    dst[(i0 >> 1)] = make_float2(r0, r1);
}

// ---------------------------------------------------------------------------
// Kernel 2: fused logit + softmax + write, ONE WARP PER K (no block barriers
// after staging). Grid (32 kg, 32 b) x 256 threads. Block stages
// (s_i, B'_i) float2 pairs in smem (B' = Bsum*log2e, summed from the two
// j-half partials); each warp streams 2048 dims into 64 regs, warp-reduces
// max/sum via shuffles, EX2, scales, stores 8KB row.
// ---------------------------------------------------------------------------
__global__ __launch_bounds__(256, 2) void softmax_kernel(const float* __restrict__ scores,
                                                         float* __restrict__ out) {
    __shared__ float2 sb[DIM];           // 16KB: (s_i, B'_i)
    const int kg = blockIdx.x;           // k group of 8
    const int b  = blockIdx.y;
    const int t  = threadIdx.x;

    {   // stage: 256 threads x 8 elements
        const float4* sc4 = (const float4*)(scores + (b << 11));
        const float4* p0  = (const float4*)(g_part + (b << 11));
        const float4* p1  = (const float4*)(g_part + ((BATCH + b) << 11));
        float4* sb4 = (float4*)sb;
        #pragma unroll
        for (int c = 0; c < 2; c++) {
            int j = t + c * 256;
            float4 s = sc4[j], u = p0[j], v = p1[j];
            sb4[j * 2 + 0] = make_float4(s.x, u.x + v.x, s.y, u.y + v.y);
            sb4[j * 2 + 1] = make_float4(s.z, u.z + v.z, s.w, u.w + v.w);
        }
    }
    __syncthreads();

    const int w = t >> 5, lane = t & 31;
    const int k = (kg << 3) + w;
    const float scal2 = (float)(DIM - 1 - 2 * k) * LOG2E;

    const float4* sb4 = (const float4*)sb;

    float l[64];
    #pragma unroll
    for (int it = 0; it < 16; it++) {
        int base = it * 64 + lane * 2;   // lane handles i = it*128 + lane*4 ..+3
        float4 u = sb4[base];
        float4 v = sb4[base + 1];
        l[it * 4 + 0] = fmaf(u.x, scal2, -u.y);
        l[it * 4 + 1] = fmaf(u.z, scal2, -u.w);
        l[it * 4 + 2] = fmaf(v.x, scal2, -v.y);
        l[it * 4 + 3] = fmaf(v.z, scal2, -v.w);
    }

    // warp max: 8 partial chains then fold, then butterfly
    float M;
    {
        float p[8];
        #pragma unroll
        for (int c = 0; c < 8; c++) {
            float m = l[c * 8];
            #pragma unroll
            for (int i = 1; i < 8; i++) m = fmaxf(m, l[c * 8 + i]);
            p[c] = m;
        }
        float m = fmaxf(fmaxf(fmaxf(p[0], p[1]), fmaxf(p[2], p[3])),
                        fmaxf(fmaxf(p[4], p[5]), fmaxf(p[6], p[7])));
        #pragma unroll
        for (int o = 16; o; o >>= 1) m = fmaxf(m, __shfl_xor_sync(0xffffffffu, m, o));
        M = m;
    }

    // exp2 + warp sum (4 partial chains)
    float S;
    {
        float s0 = 0.f, s1 = 0.f, s2 = 0.f, s3 = 0.f;
        #pragma unroll
        for (int c = 0; c < 16; c++) {
            float e0 = ex2f(l[c * 4 + 0] - M);
            float e1 = ex2f(l[c * 4 + 1] - M);
            float e2 = ex2f(l[c * 4 + 2] - M);
            float e3 = ex2f(l[c * 4 + 3] - M);
            l[c * 4 + 0] = e0; s0 += e0;
            l[c * 4 + 1] = e1; s1 += e1;
            l[c * 4 + 2] = e2; s2 += e2;
            l[c * 4 + 3] = e3; s3 += e3;
        }
        float s = (s0 + s1) + (s2 + s3);
        #pragma unroll
        for (int o = 16; o; o >>= 1) s += __shfl_xor_sync(0xffffffffu, s, o);
        S = s;
    }

    const float inv = rcpf(S);

    float4* out4 = (float4*)(out + ((size_t)((b << 8) + k) << 11));
    #pragma unroll
    for (int it = 0; it < 16; it++) {
        out4[it * 32 + lane] = make_float4(l[it * 4 + 0] * inv,
                                           l[it * 4 + 1] * inv,
                                           l[it * 4 + 2] * inv,
                                           l[it * 4 + 3] * inv);
    }
}

extern "C" void kernel_launch(void* const* d_in, const int* in_sizes, int n_in,
                              void* d_out, int out_size) {
    const float* scores = (const float*)d_in[0];
    float* out = (float*)d_out;

    bsum_kernel<<<dim3(DIM / 64, 2, BATCH), 32>>>(scores);
    softmax_kernel<<<dim3(KTOP / 8, BATCH), 256>>>(scores, out);
}